// round 6
// baseline (speedup 1.0000x reference)
#include <cuda_runtime.h>
#include <cuda_bf16.h>

// MedianFilter1D: k=9 sliding median, replicate padding. x: [2048 rows, 8192].
//
// R6: barrier-free (R4 structure, best issue% observed) with the edge-clamp
// path moved to DEDICATED threads behind an early return so it cannot be
// if-converted into the interior path (R4's 1.7x alu-cycle bloat).
// Interior thread: 3 overlapping coalesced LDG.128 -> 66 FMNMX -> 1 STG.128.
// No smem, no __syncthreads, no phase serialization.

#define ROW_L 8192
#define QPR   2048          // output quads per row
#define NT    256

__device__ __forceinline__ void cswap(float& a, float& b) {
    float lo = fminf(a, b);
    b = fmaxf(a, b);
    a = lo;
}

__device__ __forceinline__ void sort3(float& a, float& b, float& c) {
    cswap(a, b);
    cswap(b, c);
    cswap(a, b);
}

__device__ __forceinline__ float med3(float a, float b, float c) {
    return fmaxf(fminf(a, b), fminf(fmaxf(a, b), c));
}

// One output: insert x into sorted pair (p0<=p1), combine with hoisted
// shared-triple reductions (mm, nn, p, qp1=min(q,p1)). 11 ops.
__device__ __forceinline__ float median_out(float x, float p0, float p1,
                                            float mm, float nn,
                                            float p, float qp1) {
    float a0 = fminf(x, p0);
    float m  = fmaxf(x, p0);
    float lo  = fmaxf(a0, mm);
    float mid = fmaxf(p, fminf(qp1, m));
    float hi  = fminf(fmaxf(m, p1), nn);
    return med3(lo, mid, hi);
}

// 4 outputs (base position = va's first element + 4) from 12 consecutive
// values va|vb|vc. 66 min/max ops. (Identity verified R2..R5, rel_err 0.)
__device__ __forceinline__ float4 median4(float4 va, float4 vb, float4 vc) {
    float b0 = va.w, b1 = vb.x, b2 = vb.y; sort3(b0, b1, b2);  // T1 {v3,v4,v5}
    float c0 = vb.z, c1 = vb.w, c2 = vc.x; sort3(c0, c1, c2);  // T2 {v6,v7,v8}
    const float mm = fmaxf(b0, c0);
    const float nn = fminf(b2, c2);
    const float p  = fminf(b1, c1);
    const float q  = fmaxf(b1, c1);
    float s1 = fminf(va.y, va.z), s2 = fmaxf(va.y, va.z);      // (v1,v2)
    float t1 = fminf(vc.y, vc.z), t2 = fmaxf(vc.y, vc.z);      // (v9,v10)
    const float qs2 = fminf(q, s2);
    const float qt2 = fminf(q, t2);
    float4 r;
    r.x = median_out(va.x, s1, s2, mm, nn, p, qs2);            // {v0,v1,v2}+T1+T2
    r.y = median_out(vc.y, s1, s2, mm, nn, p, qs2);            // {v1,v2,v9}+T1+T2
    r.z = median_out(va.z, t1, t2, mm, nn, p, qt2);            // {v2,v9,v10}+T1+T2
    r.w = median_out(vc.w, t1, t2, mm, nn, p, qt2);            // {v9,v10,v11}+T1+T2
    return r;
}

__global__ __launch_bounds__(NT, 6)
void median9_kernel(const float* __restrict__ x, float* __restrict__ y) {
    const int row = blockIdx.y;
    const int tr  = blockIdx.x * NT + threadIdx.x;   // quad index in row, 0..2047
    const float* __restrict__ xr = x + ((size_t)row << 13);
    float* __restrict__ yr       = y + ((size_t)row << 13);

    if (tr == 0 || tr == QPR - 1) {
        // Edge quads (2 threads/row): clamped scalar loads, then same math.
        // Early return => separate code region, not predicatable into the
        // interior path.
        const int m = tr ? (ROW_L - 4) : 0;
        float v[12];
        #pragma unroll
        for (int i = 0; i < 12; i++) {
            int idx = m - 4 + i;
            idx = min(max(idx, 0), ROW_L - 1);
            v[i] = __ldg(xr + idx);
        }
        float4 qa = make_float4(v[0], v[1], v[2],  v[3]);
        float4 qb = make_float4(v[4], v[5], v[6],  v[7]);
        float4 qc = make_float4(v[8], v[9], v[10], v[11]);
        *(float4*)(yr + m) = median4(qa, qb, qc);
        return;
    }

    // Interior: window for outputs [4tr, 4tr+4) is x[4tr-4 .. 4tr+11].
    // 3 aligned, lane-coalesced LDG.128 (16B stride across lanes).
    const int m = 4 * tr;
    const float4* p4 = (const float4*)(xr + m - 4);
    float4 qa = p4[0];
    float4 qb = p4[1];
    float4 qc = p4[2];

    *(float4*)(yr + m) = median4(qa, qb, qc);
}

extern "C" void kernel_launch(void* const* d_in, const int* in_sizes, int n_in,
                              void* d_out, int out_size) {
    const float* x = (const float*)d_in[0];
    float* y = (float*)d_out;
    const int rows = in_sizes[0] / ROW_L;            // B*C = 2048
    dim3 grid(QPR / NT, rows);                       // (8, 2048)
    median9_kernel<<<grid, NT>>>(x, y);
}